// round 11
// baseline (speedup 1.0000x reference)
#include <cuda_runtime.h>
#include <cuda_fp16.h>
#include <cstdint>

#define NB 8
#define NC 256
#define ND 2048
typedef __half fp16;

// ---------------- static scratch ----------------
__device__ __align__(128) fp16  g_xt[NB * ND * NC];
__device__ __align__(128) float g_sq[NB * ND];
__device__ __align__(128) fp16  g_w[NC * NC];
__device__ __align__(128) fp16  g_xf[NB * NC * ND];    // [b][o][d]
__device__ __align__(128) fp16  g_hg[(size_t)NB * ND * ND];
__device__ __align__(128) float g_deg[NB * ND];
__device__ __align__(128) float g_inv[NB * ND];
__device__ __align__(128) fp16  g_E[NB * NC * ND];     // [b][o][d]

// ---------------- helpers ----------------
__device__ __forceinline__ uint32_t smem_u32(const void* p) {
    uint32_t a;
    asm("{ .reg .u64 t; cvta.to.shared.u64 t, %1; cvt.u32.u64 %0, t; }" : "=r"(a) : "l"(p));
    return a;
}
#define SW128(x) ((x) ^ (((x) >> 3) & 0x70))

__device__ __forceinline__ void cp16(uint32_t dst, const void* src) {
    asm volatile("cp.async.cg.shared.global [%0], [%1], 16;\n" :: "r"(dst), "l"(src));
}
__device__ __forceinline__ void cpa_commit() { asm volatile("cp.async.commit_group;\n" ::: "memory"); }
template <int N>
__device__ __forceinline__ void cpa_waitN() { asm volatile("cp.async.wait_group %0;\n" :: "n"(N) : "memory"); }

__device__ __forceinline__ void ldm4(uint32_t* r, uint32_t addr) {
    asm volatile("ldmatrix.sync.aligned.m8n8.x4.shared.b16 {%0,%1,%2,%3}, [%4];"
                 : "=r"(r[0]), "=r"(r[1]), "=r"(r[2]), "=r"(r[3]) : "r"(addr));
}
__device__ __forceinline__ void mma16816(float* d, const uint32_t* a, const uint32_t* b) {
    asm volatile(
        "mma.sync.aligned.m16n8k16.row.col.f32.f16.f16.f32 "
        "{%0,%1,%2,%3}, {%4,%5,%6,%7}, {%8,%9}, {%0,%1,%2,%3};"
        : "+f"(d[0]), "+f"(d[1]), "+f"(d[2]), "+f"(d[3])
        : "r"(a[0]), "r"(a[1]), "r"(a[2]), "r"(a[3]), "r"(b[0]), "r"(b[1]));
}
__device__ __forceinline__ uint32_t pk2(fp16 a, fp16 b) {
    return (uint32_t)__half_as_ushort(a) | ((uint32_t)__half_as_ushort(b) << 16);
}

// load one 128-row x 64-col fp16 chunk into SW128 smem tile (256 threads)
__device__ __forceinline__ void load_tile256(uint32_t tb, const fp16* g, size_t rs, int kc, int t) {
#pragma unroll
    for (int i = 0; i < 4; i++) {
        int lin = i * 256 + t;
        int row = lin >> 3, seg = lin & 7;
        cp16(tb + SW128((uint32_t)(row * 128 + seg * 16)), g + (size_t)row * rs + kc + seg * 8);
    }
}

// ---------------- block GEMM mainloop (1 A tile, 1 B tile, K64 chunks) ----------------
template <int NSTAGES>
__device__ __forceinline__ void gemm_main(
    uint32_t sb, const fp16* A0, const fp16* B0,
    size_t sA, size_t sB, int nchunks, float acc[2][8][4])
{
    const uint32_t TS = 16384u;
    const uint32_t STAGE = 2 * TS;
    int t = threadIdx.x;
    int lane = t & 31, wid = t >> 5;
    int warp_m = (wid & 3) * 32, warp_n = (wid >> 2) * 64;
    int lrow = lane & 15;
    int lcol = (lane & 16) ? 16 : 0;

#pragma unroll
    for (int s = 0; s < NSTAGES - 1; s++) {
        uint32_t st = sb + (uint32_t)s * STAGE;
        int kc = s * 64;
        load_tile256(st, A0, sA, kc, t);
        load_tile256(st + TS, B0, sB, kc, t);
        cpa_commit();
    }
    for (int c = 0; c < nchunks; c++) {
        uint32_t cur = sb + (uint32_t)(c % NSTAGES) * STAGE;
        int cn = c + NSTAGES - 1;
        if (cn < nchunks) {
            uint32_t nx = sb + (uint32_t)(cn % NSTAGES) * STAGE;
            int kc = cn * 64;
            load_tile256(nx, A0, sA, kc, t);
            load_tile256(nx + TS, B0, sB, kc, t);
        }
        cpa_commit();
        cpa_waitN<NSTAGES - 1>();
        __syncthreads();
#pragma unroll
        for (int ks = 0; ks < 4; ks++) {
            int kb = ks * 32 + lcol;
            uint32_t a[2][4];
#pragma unroll
            for (int f = 0; f < 2; f++)
                ldm4(a[f], cur + SW128((uint32_t)((warp_m + f * 16 + lrow) * 128 + kb)));
            uint32_t bfr[8][2];
#pragma unroll
            for (int np = 0; np < 4; np++) {
                uint32_t r[4];
                ldm4(r, cur + TS + SW128((uint32_t)((warp_n + np * 16 + lrow) * 128 + kb)));
                bfr[2 * np][0] = r[0]; bfr[2 * np][1] = r[2];
                bfr[2 * np + 1][0] = r[1]; bfr[2 * np + 1][1] = r[3];
            }
#pragma unroll
            for (int f = 0; f < 2; f++)
#pragma unroll
                for (int nt = 0; nt < 8; nt++)
                    mma16816(acc[f][nt], a[f], bfr[nt]);
        }
        __syncthreads();
    }
}

// ---------------- GEMM kernels ----------------
// Gram + threshold + fused degree. Triangular grid: blockIdx.x in [0,136).
__global__ void __launch_bounds__(256, 2) k_gram_mma() {
    int L = blockIdx.x;
    int i = 0, rem = L;
    while (rem >= (ND / 128) - i) { rem -= (ND / 128) - i; i++; }
    int j = i + rem;

    extern __shared__ char smem[];
    uint32_t sb = smem_u32(smem);
    int b = blockIdx.z, m0 = i * 128, n0 = j * 128;
    const fp16* X = g_xt + (size_t)b * ND * NC;
    float acc[2][8][4] = {};
    gemm_main<3>(sb, X + (size_t)m0 * NC, X + (size_t)n0 * NC, NC, NC, NC / 64, acc);

    float* s_sqm = (float*)smem;
    float* s_sqn = s_sqm + 128;
    fp16* tr = (fp16*)(smem + 1024);  // [128][136] transpose staging
    int t = threadIdx.x;
    if (t < 128) s_sqm[t] = g_sq[b * ND + m0 + t];
    else s_sqn[t - 128] = g_sq[b * ND + n0 + (t - 128)];
    __syncthreads();

    int lane = t & 31, wid = t >> 5;
    int warp_m = (wid & 3) * 32, warp_n = (wid >> 2) * 64;
    int r4 = lane >> 2, c2 = (lane & 3) * 2;
    fp16* Hb = g_hg + (size_t)b * ND * ND;
    float* degb = g_deg + b * ND;
    const fp16 one = __float2half_rn(1.f), zero = __float2half_rn(0.f);
    bool mirror = (j > i);
#pragma unroll
    for (int f = 0; f < 2; f++)
#pragma unroll
        for (int h = 0; h < 2; h++) {
            int m = warp_m + f * 16 + r4 + h * 8;
            float sm = s_sqm[m];
            uint32_t* hrow = (uint32_t*)(Hb + (size_t)(m0 + m) * ND + n0);
            float cnt = 0.f;
#pragma unroll
            for (int nt = 0; nt < 8; nt++) {
                int n = warp_n + nt * 8 + c2;
                float d0 = sm + s_sqn[n] - 2.f * acc[f][nt][2 * h];
                float d1 = sm + s_sqn[n + 1] - 2.f * acc[f][nt][2 * h + 1];
                fp16 v0 = d0 < 484.f ? one : zero;
                fp16 v1 = d1 < 484.f ? one : zero;
                cnt += (d0 < 484.f ? 1.f : 0.f) + (d1 < 484.f ? 1.f : 0.f);
                hrow[n >> 1] = pk2(v0, v1);
                if (mirror) {
                    tr[(size_t)n * 136 + m] = v0;
                    tr[(size_t)(n + 1) * 136 + m] = v1;
                }
            }
            cnt += __shfl_xor_sync(0xFFFFFFFFu, cnt, 1);
            cnt += __shfl_xor_sync(0xFFFFFFFFu, cnt, 2);
            if ((lane & 3) == 0) atomicAdd(&degb[m0 + m], cnt);
        }
    if (mirror) {
        __syncthreads();
        int r = t >> 1, half = t & 1;
        uint4* dst = (uint4*)(Hb + (size_t)(n0 + r) * ND + m0 + half * 64);
        const uint4* src = (const uint4*)(tr + (size_t)r * 136 + half * 64);
        float csum = 0.f;
#pragma unroll
        for (int k = 0; k < 8; k++) {
            uint4 v = src[k];
            dst[k] = v;
            uint32_t u[4] = {v.x, v.y, v.z, v.w};
#pragma unroll
            for (int q = 0; q < 4; q++) {
                float2 fv = __half22float2(*(half2*)&u[q]);
                csum += fv.x + fv.y;
            }
        }
        atomicAdd(&degb[n0 + r], csum);
    }
}

// FC: xf_T[o][d] = sum_c W[o][c]*xt[d][c] + bias[o]
__global__ void __launch_bounds__(256, 2) k_fc_mma(const float* __restrict__ bias) {
    extern __shared__ char smem[];
    uint32_t sb = smem_u32(smem);
    int b = blockIdx.z, m0 = blockIdx.y * 128, n0 = blockIdx.x * 128;
    const fp16* X = g_xt + (size_t)b * ND * NC;
    float acc[2][8][4] = {};
    gemm_main<3>(sb, g_w + (size_t)m0 * NC, X + (size_t)n0 * NC, NC, NC, NC / 64, acc);

    int t = threadIdx.x;
    int lane = t & 31, wid = t >> 5;
    int warp_m = (wid & 3) * 32, warp_n = (wid >> 2) * 64;
    int r4 = lane >> 2, c2 = (lane & 3) * 2;
#pragma unroll
    for (int f = 0; f < 2; f++)
#pragma unroll
        for (int h = 0; h < 2; h++) {
            int m = warp_m + f * 16 + r4 + h * 8;
            float bv = bias[m0 + m];
            uint32_t* rh = (uint32_t*)(g_xf + ((size_t)b * NC + m0 + m) * ND + n0);
#pragma unroll
            for (int nt = 0; nt < 8; nt++) {
                int n = warp_n + nt * 8 + c2;
                rh[n >> 1] = pk2(__float2half_rn(acc[f][nt][2 * h] + bv),
                                 __float2half_rn(acc[f][nt][2 * h + 1] + bv));
            }
        }
}

// AGG: D[o][n] = sum_k S[o][k]*hg[n][k]; scale by inv[n]; FINAL adds residual x.
template <bool FINAL>
__global__ void __launch_bounds__(256, 2) k_agg_mma(const float* __restrict__ xres,
                                                    float* __restrict__ out) {
    extern __shared__ char smem[];
    uint32_t sb = smem_u32(smem);
    int b = blockIdx.z, m0 = blockIdx.y * 128, n0 = blockIdx.x * 128;
    const fp16* S = (FINAL ? g_E : g_xf) + (size_t)b * NC * ND;
    const fp16* H = g_hg + (size_t)b * ND * ND;
    float acc[2][8][4] = {};
    gemm_main<3>(sb, S + (size_t)m0 * ND, H + (size_t)n0 * ND, ND, ND, ND / 64, acc);

    float* s_inv = (float*)smem;
    int t = threadIdx.x;
    if (t < 128) s_inv[t] = g_inv[b * ND + n0 + t];
    __syncthreads();

    int lane = t & 31, wid = t >> 5;
    int warp_m = (wid & 3) * 32, warp_n = (wid >> 2) * 64;
    int r4 = lane >> 2, c2 = (lane & 3) * 2;
#pragma unroll
    for (int f = 0; f < 2; f++)
#pragma unroll
        for (int h = 0; h < 2; h++) {
            int m = warp_m + f * 16 + r4 + h * 8;
            if (!FINAL) {
                uint32_t* rh = (uint32_t*)(g_E + ((size_t)b * NC + m0 + m) * ND + n0);
#pragma unroll
                for (int nt = 0; nt < 8; nt++) {
                    int n = warp_n + nt * 8 + c2;
                    rh[n >> 1] = pk2(__float2half_rn(acc[f][nt][2 * h] * s_inv[n]),
                                     __float2half_rn(acc[f][nt][2 * h + 1] * s_inv[n + 1]));
                }
            } else {
                const float* xrow = xres + ((size_t)b * NC + m0 + m) * ND + n0;
                float* orow = out + ((size_t)b * NC + m0 + m) * ND + n0;
#pragma unroll
                for (int nt = 0; nt < 8; nt++) {
                    int n = warp_n + nt * 8 + c2;
                    float2 xv = *(const float2*)(xrow + n);
                    float2 o;
                    o.x = acc[f][nt][2 * h] * s_inv[n] + xv.x;
                    o.y = acc[f][nt][2 * h + 1] * s_inv[n + 1] + xv.y;
                    *(float2*)(orow + n) = o;
                }
            }
        }
}

// ---------------- prep / small kernels ----------------
__global__ void k_prep_xt(const float* __restrict__ x) {
    __shared__ float tile[32][33];
    int b = blockIdx.z;
    int d0 = blockIdx.x * 32, c0 = blockIdx.y * 32;
    const float* xb = x + (size_t)b * NC * ND;
    int tx = threadIdx.x, ty = threadIdx.y;  // 32x8
#pragma unroll
    for (int i = 0; i < 32; i += 8)
        tile[ty + i][tx] = xb[(size_t)(c0 + ty + i) * ND + d0 + tx];
    __syncthreads();
    fp16* oh = g_xt + (size_t)b * ND * NC;
#pragma unroll
    for (int i = 0; i < 32; i += 8)
        oh[(size_t)(d0 + ty + i) * NC + c0 + tx] = __float2half_rn(tile[tx][ty + i]);
}

__global__ void __launch_bounds__(256) k_sq(const float* __restrict__ x) {
    int gid = blockIdx.x * 256 + threadIdx.x;  // b*ND + d
    int b = gid >> 11, d = gid & (ND - 1);
    const float* xb = x + (size_t)b * NC * ND + d;
    float s = 0.f;
#pragma unroll 8
    for (int c = 0; c < NC; c++) {
        float v = xb[(size_t)c * ND];
        s += v * v;
    }
    g_sq[gid] = s;
    g_deg[gid] = 0.f;  // zero for gram's fused-degree atomics
}

__global__ void __launch_bounds__(256) k_prep_w(const float* __restrict__ W) {
    int i = blockIdx.x * 256 + threadIdx.x;
    g_w[i] = __float2half_rn(W[i]);
}

__global__ void __launch_bounds__(256) k_inv() {
    int gid = blockIdx.x * 256 + threadIdx.x;
    float d = g_deg[gid];
    g_inv[gid] = (d > 0.f) ? (1.f / d) : 0.f;
}

__global__ void __launch_bounds__(256) k_ln(float* __restrict__ out,
                                            const float* __restrict__ gamma,
                                            const float* __restrict__ beta) {
    int row = blockIdx.x;  // b*NC + c
    float* p = out + (size_t)row * ND;
    int t = threadIdx.x;
    float4 v0 = *(float4*)(p + t * 8);
    float4 v1 = *(float4*)(p + t * 8 + 4);
    float vals[8] = {v0.x, v0.y, v0.z, v0.w, v1.x, v1.y, v1.z, v1.w};
    float s = 0.f, s2 = 0.f;
#pragma unroll
    for (int u = 0; u < 8; u++) {
        s += vals[u];
        s2 += vals[u] * vals[u];
    }
    __shared__ float r1[256];
    __shared__ float r2[256];
    r1[t] = s;
    r2[t] = s2;
    __syncthreads();
    for (int o = 128; o > 0; o >>= 1) {
        if (t < o) {
            r1[t] += r1[t + o];
            r2[t] += r2[t + o];
        }
        __syncthreads();
    }
    float mean = r1[0] * (1.f / ND);
    float var = r2[0] * (1.f / ND) - mean * mean;
    float rstd = rsqrtf(var + 1e-5f);
#pragma unroll
    for (int u = 0; u < 8; u++) {
        int d = t * 8 + u;
        float yn = (vals[u] - mean) * rstd * gamma[d] + beta[d];
        vals[u] = yn / (1.f + expf(-yn));
    }
    v0.x = vals[0]; v0.y = vals[1]; v0.z = vals[2]; v0.w = vals[3];
    v1.x = vals[4]; v1.y = vals[5]; v1.z = vals[6]; v1.w = vals[7];
    *(float4*)(p + t * 8) = v0;
    *(float4*)(p + t * 8 + 4) = v1;
}

// ---------------- launch ----------------
extern "C" void kernel_launch(void* const* d_in, const int* in_sizes, int n_in,
                              void* d_out, int out_size) {
    const float* x = (const float*)d_in[0];
    const float* W = (const float*)d_in[1];
    const float* bias = (const float*)d_in[2];
    const float* gamma = (const float*)d_in[3];
    const float* beta = (const float*)d_in[4];
    float* out = (float*)d_out;
    (void)in_sizes; (void)n_in; (void)out_size;

    const int SMEM_G = 3 * 2 * 16384;  // 98304 (3 stages x 2 K64-tiles) — all GEMMs
    static bool attr_set = false;
    if (!attr_set) {
        cudaFuncSetAttribute(k_gram_mma, cudaFuncAttributeMaxDynamicSharedMemorySize, SMEM_G);
        cudaFuncSetAttribute(k_fc_mma, cudaFuncAttributeMaxDynamicSharedMemorySize, SMEM_G);
        cudaFuncSetAttribute(k_agg_mma<false>, cudaFuncAttributeMaxDynamicSharedMemorySize, SMEM_G);
        cudaFuncSetAttribute(k_agg_mma<true>, cudaFuncAttributeMaxDynamicSharedMemorySize, SMEM_G);
        attr_set = true;
    }

    const int NTRI = (ND / 128) * (ND / 128 + 1) / 2;  // 136

    k_prep_xt<<<dim3(ND / 32, NC / 32, NB), dim3(32, 8)>>>(x);
    k_sq<<<NB * ND / 256, 256>>>(x);
    k_prep_w<<<NC * NC / 256, 256>>>(W);
    k_gram_mma<<<dim3(NTRI, 1, NB), 256, SMEM_G>>>();
    k_inv<<<NB * ND / 256, 256>>>();
    k_fc_mma<<<dim3(ND / 128, NC / 128, NB), 256, SMEM_G>>>(bias);
    k_agg_mma<false><<<dim3(ND / 128, NC / 128, NB), 256, SMEM_G>>>(nullptr, nullptr);
    k_agg_mma<true><<<dim3(ND / 128, NC / 128, NB), 256, SMEM_G>>>(x, out);
    k_ln<<<NB * NC, 256>>>(out, gamma, beta);
}